// round 17
// baseline (speedup 1.0000x reference)
#include <cuda_runtime.h>
#include <cuda_fp16.h>
#include <cstdint>

#define BATCH 512
#define NNEG  2048
#define EDIM  256
#define KDIM  512           // pure fp16: K = 2*E
#define KC    128           // fp16 K per chunk (2 x 64 sub-slabs)
#define NCH   (KDIM / KC)   // 4 chunks
#define STG   3

// Scratch
__device__ __align__(16) __half g_Ah[BATCH * KDIM];
__device__ __align__(16) __half g_Bh[NNEG  * KDIM];
__device__ float g_c[BATCH];
__device__ unsigned long long g_gen;       // 1024 tickets per launch
__device__ unsigned int g_rA[16];          // A m-block readiness (16 producers each)
__device__ unsigned int g_rB[64];          // B n-block readiness (4 producers each)

#define BM 32
#define BN 32
#define STAGE_BYTES 16384                  // A 2x4KB + B 2x4KB
#define SM_TOTAL    (STG * STAGE_BYTES)    // 48KB

__device__ __forceinline__ uint32_t s2u(const void* p) {
    uint32_t a;
    asm("{ .reg .u64 t; cvta.to.shared.u64 t, %1; cvt.u32.u64 %0, t; }" : "=r"(a) : "l"(p));
    return a;
}
__device__ __forceinline__ uint32_t sw128(uint32_t off) {
    return off ^ ((off >> 3) & 0x70);
}
__device__ __forceinline__ void cpasync16(uint32_t dst, const void* src) {
    asm volatile("cp.async.cg.shared.global [%0], [%1], 16;" :: "r"(dst), "l"(src));
}
__device__ __forceinline__ float wredsum(float v) {
    #pragma unroll
    for (int o = 16; o > 0; o >>= 1) v += __shfl_xor_sync(0xffffffffu, v, o);
    return v;
}
__device__ __forceinline__ uint4 pack8(const float* v) {
    union { uint4 u; __half2 h[4]; } r;
    r.h[0] = __floats2half2_rn(v[0], v[1]);
    r.h[1] = __floats2half2_rn(v[2], v[3]);
    r.h[2] = __floats2half2_rn(v[4], v[5]);
    r.h[3] = __floats2half2_rn(v[6], v[7]);
    return r.u;
}
__device__ __forceinline__ unsigned int ld_acq_u32(const unsigned int* p) {
    unsigned int v;
    asm volatile("ld.acquire.gpu.global.u32 %0, [%1];" : "=r"(v) : "l"(p));
    return v;
}

// ---------------------------------------------------------------------------
// 1024-CTA fused kernel: bids<256 prep (R12 pattern) -> group readiness ->
// one 32x32 tile per CTA.
// ---------------------------------------------------------------------------
__global__ void __launch_bounds__(128, 4)
fused_kernel(float* __restrict__ out,
             const float* __restrict__ head,
             const float* __restrict__ tail,
             const float* __restrict__ rel,
             const int* __restrict__ rid) {
    extern __shared__ __align__(128) char smem[];
    __shared__ unsigned long long gen_sh;

    int tid = threadIdx.x;
    int lane = tid & 31;
    int wid = tid >> 5;                        // 0..3
    int bx = blockIdx.x;                       // 0..63 (n-tile)
    int by = blockIdx.y;                       // 0..15 (m-tile)
    int bid = by * 64 + bx;                    // linear; wave-1 contains bids<~592
    int e0 = lane * 8;

    // ======== Phase 1: prep (bids 0..255 only; R12 pattern: 2 A + 8 B rows) ==
    if (bid < 256) {
        int flat = bid;
        bool hasA = (wid < 2);
        int b  = flat * 2 + wid;
        int j0 = flat * 8 + wid;
        int j1 = j0 + 4;

        float hv[8];
        int r = 0;
        if (hasA) {
            *reinterpret_cast<float4*>(hv)     = *reinterpret_cast<const float4*>(&head[b * EDIM + e0]);
            *reinterpret_cast<float4*>(hv + 4) = *reinterpret_cast<const float4*>(&head[b * EDIM + e0 + 4]);
            r = __ldg(&rid[b]);
        }
        float tv0[8], tv1[8];
        *reinterpret_cast<float4*>(tv0)     = *reinterpret_cast<const float4*>(&tail[j0 * EDIM + e0]);
        *reinterpret_cast<float4*>(tv0 + 4) = *reinterpret_cast<const float4*>(&tail[j0 * EDIM + e0 + 4]);
        *reinterpret_cast<float4*>(tv1)     = *reinterpret_cast<const float4*>(&tail[j1 * EDIM + e0]);
        *reinterpret_cast<float4*>(tv1 + 4) = *reinterpret_cast<const float4*>(&tail[j1 * EDIM + e0 + 4]);

        float rh[8], rt[8];
        if (hasA) {
            const float* rrow = rel + (size_t)r * KDIM;
            *reinterpret_cast<float4*>(rh)     = *reinterpret_cast<const float4*>(&rrow[e0]);
            *reinterpret_cast<float4*>(rh + 4) = *reinterpret_cast<const float4*>(&rrow[e0 + 4]);
            *reinterpret_cast<float4*>(rt)     = *reinterpret_cast<const float4*>(&rrow[EDIM + e0]);
            *reinterpret_cast<float4*>(rt + 4) = *reinterpret_cast<const float4*>(&rrow[EDIM + e0 + 4]);
        }
        {
            float s = 0.f;
            #pragma unroll
            for (int i = 0; i < 8; i++) s += tv0[i] * tv0[i];
            s = wredsum(s);
            float inv = 1.f / fmaxf(sqrtf(s), 1e-12f);
            float w1[8], w2[8];
            #pragma unroll
            for (int i = 0; i < 8; i++) {
                float tn = tv0[i] * inv;
                w1[i] = tn * tn;
                w2[i] = tn;
            }
            size_t rb = (size_t)j0 * KDIM;
            *reinterpret_cast<uint4*>(&g_Bh[rb + e0])        = pack8(w1);
            *reinterpret_cast<uint4*>(&g_Bh[rb + EDIM + e0]) = pack8(w2);
        }
        {
            float s = 0.f;
            #pragma unroll
            for (int i = 0; i < 8; i++) s += tv1[i] * tv1[i];
            s = wredsum(s);
            float inv = 1.f / fmaxf(sqrtf(s), 1e-12f);
            float w1[8], w2[8];
            #pragma unroll
            for (int i = 0; i < 8; i++) {
                float tn = tv1[i] * inv;
                w1[i] = tn * tn;
                w2[i] = tn;
            }
            size_t rb = (size_t)j1 * KDIM;
            *reinterpret_cast<uint4*>(&g_Bh[rb + e0])        = pack8(w1);
            *reinterpret_cast<uint4*>(&g_Bh[rb + EDIM + e0]) = pack8(w2);
        }
        if (hasA) {
            float s = 0.f;
            #pragma unroll
            for (int i = 0; i < 8; i++) s += hv[i] * hv[i];
            s = wredsum(s);
            float inv = 1.f / fmaxf(sqrtf(s), 1e-12f);
            float v1[8], v2[8], cs = 0.f;
            #pragma unroll
            for (int i = 0; i < 8; i++) {
                float hh = hv[i] * inv * rh[i];
                v1[i] = rt[i] * rt[i];
                v2[i] = -2.f * rt[i] * hh;
                cs += hh * hh;
            }
            size_t ra = (size_t)b * KDIM;
            *reinterpret_cast<uint4*>(&g_Ah[ra + e0])        = pack8(v1);
            *reinterpret_cast<uint4*>(&g_Ah[ra + EDIM + e0]) = pack8(v2);
            cs = wredsum(cs);
            if (lane == 0) g_c[b] = cs;
        }
        __threadfence();
    }

    // ======== Phase 2: readiness (monotonic counters; replay-safe) ========
    __syncthreads();
    if (tid == 0) {
        unsigned long long ticket = atomicAdd(&g_gen, 1ULL);
        unsigned long long gen = ticket >> 10;             // 1024 tickets/launch
        if (bid < 256) {
            atomicAdd(&g_rA[bid >> 4], 1u);                // A m-block bid/16
            atomicAdd(&g_rB[bid >> 2], 1u);                // B n-block bid/4
        }
        unsigned int tgtA = (unsigned int)((gen + 1) * 16);
        unsigned int tgtB = (unsigned int)((gen + 1) * 4);
        while ((int)(ld_acq_u32(&g_rA[by]) - tgtA) < 0) __nanosleep(32);
        while ((int)(ld_acq_u32(&g_rB[bx]) - tgtB) < 0) __nanosleep(32);
        gen_sh = gen;
    }
    __syncthreads();

    // ======== Phase 3: one 32x32 tile ========
    int wm = wid & 1;                  // 2 m-warps x 16 rows
    int wn = wid >> 1;                 // 2 n-warps x 16 cols
    int m0 = by * BM;
    int n0 = bx * BN;
    int groupID = lane >> 2;
    int tig = lane & 3;
    uint32_t sbase = s2u(smem);

    int aRow = (lane & 7) + ((lane >> 3) & 1) * 8;
    int aKh  = (lane >> 4) * 8;
    int bRowOff = ((lane >> 4) & 1) * 8 + (lane & 7);
    int bKh     = ((lane >> 3) & 1) * 8;

    auto issue = [&](int ic) {
        if (ic < NCH) {
            uint32_t sD = sbase + (ic % STG) * STAGE_BYTES;
            int k0 = ic * KC;
            #pragma unroll
            for (int h = 0; h < 2; h++) {
                uint32_t aD = sD + h * 4096;
                uint32_t bD = sD + 8192 + h * 4096;
                int kh = k0 + h * 64;
                #pragma unroll
                for (int i = 0; i < 2; i++) {
                    int idx = i * 128 + tid;           // 0..255
                    int r = idx >> 3, c = idx & 7;     // r:0..31
                    cpasync16(aD + sw128(r * 128 + c * 16),
                              &g_Ah[(size_t)(m0 + r) * KDIM + kh + c * 8]);
                    cpasync16(bD + sw128(r * 128 + c * 16),
                              &g_Bh[(size_t)(n0 + r) * KDIM + kh + c * 8]);
                }
            }
        }
        asm volatile("cp.async.commit_group;" ::: "memory");
    };

    issue(0);
    issue(1);

    // epilogue constants (A producers for m-block done per rA wait)
    float c0 = g_c[m0 + wm * 16 + groupID];
    float c1 = g_c[m0 + wm * 16 + groupID + 8];

    float acc[2][4];
    #pragma unroll
    for (int ni = 0; ni < 2; ni++)
        #pragma unroll
        for (int q = 0; q < 4; q++) acc[ni][q] = 0.f;

    #pragma unroll
    for (int it = 0; it < NCH; it++) {
        asm volatile("cp.async.wait_group 1;" ::: "memory");
        __syncthreads();
        issue(it + 2);

        uint32_t sB = sbase + (it % STG) * STAGE_BYTES;

        #pragma unroll
        for (int kk = 0; kk < 8; kk++) {       // 8 k-steps of 16
            uint32_t aBase = sB + (kk >> 2) * 4096;
            uint32_t bBase = sB + 8192 + (kk >> 2) * 4096;
            int kq = kk & 3;

            uint32_t af[4];
            {
                int row = wm * 16 + aRow;
                int kcol = kq * 16 + aKh;
                uint32_t addr = aBase + sw128((uint32_t)(row * 128 + kcol * 2));
                asm volatile(
                    "ldmatrix.sync.aligned.m8n8.x4.shared.b16 {%0,%1,%2,%3}, [%4];"
                    : "=r"(af[0]), "=r"(af[1]), "=r"(af[2]), "=r"(af[3])
                    : "r"(addr));
            }
            uint32_t bf[2][2];
            {
                int n = wn * 16 + bRowOff;
                int kcol = kq * 16 + bKh;
                uint32_t addr = bBase + sw128((uint32_t)(n * 128 + kcol * 2));
                asm volatile(
                    "ldmatrix.sync.aligned.m8n8.x4.shared.b16 {%0,%1,%2,%3}, [%4];"
                    : "=r"(bf[0][0]), "=r"(bf[0][1]),
                      "=r"(bf[1][0]), "=r"(bf[1][1])
                    : "r"(addr));
            }
            #pragma unroll
            for (int ni = 0; ni < 2; ni++) {
                asm volatile(
                    "mma.sync.aligned.m16n8k16.row.col.f32.f16.f16.f32 "
                    "{%0,%1,%2,%3}, {%4,%5,%6,%7}, {%8,%9}, {%0,%1,%2,%3};"
                    : "+f"(acc[ni][0]), "+f"(acc[ni][1]),
                      "+f"(acc[ni][2]), "+f"(acc[ni][3])
                    : "r"(af[0]), "r"(af[1]), "r"(af[2]), "r"(af[3]),
                      "r"(bf[ni][0]), "r"(bf[ni][1]));
            }
        }
    }

    // epilogue
    int r0 = m0 + wm * 16 + groupID;
    int r1 = r0 + 8;
    #pragma unroll
    for (int ni = 0; ni < 2; ni++) {
        int col = n0 + wn * 16 + ni * 8 + tig * 2;
        float2 v0, v1;
        v0.x = -sqrtf(fmaxf(acc[ni][0] + c0, 0.f));
        v0.y = -sqrtf(fmaxf(acc[ni][1] + c0, 0.f));
        v1.x = -sqrtf(fmaxf(acc[ni][2] + c1, 0.f));
        v1.y = -sqrtf(fmaxf(acc[ni][3] + c1, 0.f));
        *reinterpret_cast<float2*>(out + (size_t)r0 * NNEG + col) = v0;
        *reinterpret_cast<float2*>(out + (size_t)r1 * NNEG + col) = v1;
    }
    (void)gen_sh;
}

// ---------------------------------------------------------------------------
extern "C" void kernel_launch(void* const* d_in, const int* in_sizes, int n_in,
                              void* d_out, int out_size) {
    const float* head = (const float*)d_in[0];       // (512, 256)
    const float* tail = (const float*)d_in[1];       // (1, 2048, 256)
    const float* rel  = (const float*)d_in[2];       // (1000, 512)
    const int*   rid  = (const int*)d_in[3];         // (512,) int32
    float* out = (float*)d_out;                      // (512, 2048)

    cudaFuncSetAttribute(fused_kernel,
                         cudaFuncAttributeMaxDynamicSharedMemorySize, SM_TOTAL);
    dim3 grid(NNEG / BN, BATCH / BM);                // 64 x 16 = 1024 CTAs
    fused_kernel<<<grid, 128, SM_TOTAL>>>(out, head, tail, rel, rid);
}